// round 10
// baseline (speedup 1.0000x reference)
#include <cuda_runtime.h>
#include <cuda_fp16.h>
#include <cstdint>

#define NB 8
#define HH 64
#define WW 64
#define DIM 768
#define RR 16
#define NPIX 32768
#define MOUT 2304
#define KP 32

#define STAGES 4
#define APITCH 40                         // halves per smem row (32 data + 8 pad)
#define STAGE_A_BYTES (128 * APITCH * 2)  // 10240
#define STAGE_BYTES (2 * STAGE_A_BYTES)   // 20480
#define SMEM_MMA (STAGES * STAGE_BYTES)   // 81920

#define PPITCH 776                        // k_prep smem pitch (768 + 8 halves)
#define SW_BYTES (32 * PPITCH * 2)        // 49664
#define SX_OFF SW_BYTES
#define SMEM_PREP (SW_BYTES + 64 * PPITCH * 2)   // 148992

// ------------------------- scratch (device globals) -------------------------
__device__ __align__(256) __half g_xh[NPIX * DIM];    // x in fp16
__device__ __align__(256) __half g_wth[MOUT * DIM];   // W_qkv^T fp16 [n][k]
__device__ __align__(256) float  g_aq[NPIX * RR];
__device__ __align__(256) float  g_av[NPIX * RR];
__device__ __align__(256) __half g_mqh[NPIX * KP];    // mid_q fp16, K padded 16->32
__device__ __align__(256) __half g_mvh[NPIX * KP];
__device__ __align__(256) __half g_wbtq[DIM * KP];    // Wb_q^T fp16 padded [n][k]
__device__ __align__(256) __half g_wbtv[DIM * KP];

// ------------------------------ helpers -------------------------------------
__device__ __forceinline__ uint32_t smem_u32(const void* p) {
    uint32_t a;
    asm("{ .reg .u64 t; cvta.to.shared.u64 t, %1; cvt.u32.u64 %0, t; }" : "=r"(a) : "l"(p));
    return a;
}

__device__ __forceinline__ void cp16(uint32_t dst, const void* src) {
    asm volatile("cp.async.cg.shared.global [%0], [%1], 16;" :: "r"(dst), "l"(src));
}

__device__ __forceinline__ void ldm_x4(uint32_t addr, uint32_t& r0, uint32_t& r1,
                                       uint32_t& r2, uint32_t& r3) {
    asm volatile("ldmatrix.sync.aligned.m8n8.x4.shared.b16 {%0,%1,%2,%3}, [%4];"
                 : "=r"(r0), "=r"(r1), "=r"(r2), "=r"(r3) : "r"(addr));
}

__device__ __forceinline__ void mma16816(float* c, const uint32_t* a, const uint32_t* b) {
    asm volatile(
        "mma.sync.aligned.m16n8k16.row.col.f32.f16.f16.f32 "
        "{%0,%1,%2,%3}, {%4,%5,%6,%7}, {%8,%9}, {%0,%1,%2,%3};"
        : "+f"(c[0]), "+f"(c[1]), "+f"(c[2]), "+f"(c[3])
        : "r"(a[0]), "r"(a[1]), "r"(a[2]), "r"(a[3]), "r"(b[0]), "r"(b[1]));
}

// ---------------------------------------------------------------------------
// k_prep: stage 64x768 X panel (converted to fp16) + 32x768 W panel in smem,
// ONE sync, then sync-free 48-step HMMA loop producing a_q | a_v.
// Also writes g_xh (x in fp16) on the way through.
// ---------------------------------------------------------------------------
__global__ void __launch_bounds__(256) k_prep(const float* __restrict__ x,
                                              const float* __restrict__ Wa_q,
                                              const float* __restrict__ Wa_v) {
    extern __shared__ char sm[];
    __half* sW = (__half*)sm;              // [n=32][k=768] pitch PPITCH
    __half* sX = (__half*)(sm + SX_OFF);   // [m=64][k=768] pitch PPITCH
    const uint32_t sbase = smem_u32(sm);
    const int tid = threadIdx.x;
    const int wid = tid >> 5, lane = tid & 31;
    const int m0 = blockIdx.x * 64;

    // W panel: 768x32 fused (q | v), stored transposed [n][k]
    for (int i = tid; i < DIM * 32; i += 256) {
        int k = i >> 5, n = i & 31;
        float v = (n < 16) ? Wa_q[k * RR + n] : Wa_v[k * RR + (n - 16)];
        sW[n * PPITCH + k] = __float2half_rn(v);
    }

    // X panel: warp w -> rows w*8..w*8+7; lane: row w*8+(lane>>2), col (lane&3)*4
    {
        const int row = wid * 8 + (lane >> 2);
        const int cb = (lane & 3) * 4;
        const float* xr = x + (size_t)(m0 + row) * DIM;
        __half* gx = g_xh + (size_t)(m0 + row) * DIM;
        __half* sx = sX + row * PPITCH;
        #pragma unroll 4
        for (int j = 0; j < 48; j++) {
            int col = j * 16 + cb;
            float4 f = *(const float4*)(xr + col);
            __half2 h01 = __floats2half2_rn(f.x, f.y);
            __half2 h23 = __floats2half2_rn(f.z, f.w);
            uint2 pk = make_uint2(*(uint32_t*)&h01, *(uint32_t*)&h23);
            *(uint2*)(gx + col) = pk;
            *(uint2*)(sx + col) = pk;
        }
    }
    __syncthreads();

    // GEMM: 64x32x768. 8 warps: 4 in M (16 rows each) x 2 in N (16 cols each).
    const int mrow0 = (wid >> 1) * 16;
    const int ncol0 = (wid & 1) * 16;
    const uint32_t a_row = (uint32_t)(mrow0 + (lane & 15));
    const uint32_t a_k8  = (uint32_t)((lane >> 4) * 8);
    const uint32_t b_row = (uint32_t)(ncol0 + (lane & 7) + ((lane >> 4) * 8));
    const uint32_t b_k8  = (uint32_t)(((lane >> 3) & 1) * 8);

    float acc[2][4];
    #pragma unroll
    for (int i = 0; i < 2; i++)
        #pragma unroll
        for (int j = 0; j < 4; j++) acc[i][j] = 0.f;

    #pragma unroll 4
    for (int k16 = 0; k16 < 48; k16++) {
        uint32_t a[4], b[2][2];
        uint32_t ad = sbase + SX_OFF + (a_row * PPITCH + k16 * 16 + a_k8) * 2;
        ldm_x4(ad, a[0], a[1], a[2], a[3]);
        uint32_t bd = sbase + (b_row * PPITCH + k16 * 16 + b_k8) * 2;
        ldm_x4(bd, b[0][0], b[0][1], b[1][0], b[1][1]);
        mma16816(acc[0], a, b[0]);
        mma16816(acc[1], a, b[1]);
    }

    const int grp = lane >> 2, tig = lane & 3;
    const int r0 = m0 + mrow0 + grp;
    #pragma unroll
    for (int ni = 0; ni < 2; ni++) {
        int n = ncol0 + ni * 8 + 2 * tig;
        float* o = (n < 16) ? g_aq : g_av;
        int nn = n & 15;
        *(float2*)&o[(size_t)r0 * RR + nn] = make_float2(acc[ni][0], acc[ni][1]);
        *(float2*)&o[(size_t)(r0 + 8) * RR + nn] = make_float2(acc[ni][2], acc[ni][3]);
    }
}

// ---------------------------------------------------------------------------
// W_qkv [768][2304] -> transposed fp16 [2304][768]
// ---------------------------------------------------------------------------
__global__ void k_wt(const float* __restrict__ W) {
    __shared__ float t[32][33];
    const int bx = blockIdx.x;           // MOUT/32 = 72
    const int by = blockIdx.y;           // DIM/32 = 24
    const int tx = threadIdx.x & 31, ty = threadIdx.x >> 5;
    #pragma unroll
    for (int k = 0; k < 4; k++) {
        int r = by * 32 + ty + k * 8;
        t[ty + k * 8][tx] = W[(size_t)r * MOUT + bx * 32 + tx];
    }
    __syncthreads();
    #pragma unroll
    for (int k = 0; k < 4; k++) {
        int n = bx * 32 + ty + k * 8;
        g_wth[(size_t)n * DIM + by * 32 + tx] = __float2half_rn(t[tx][ty + k * 8]);
    }
}

// ---------------------------------------------------------------------------
// Wb [16][768] -> transposed padded fp16 [768][32]
// ---------------------------------------------------------------------------
__global__ void k_wbt(const float* __restrict__ Wb_q,
                      const float* __restrict__ Wb_v) {
    const int qv = blockIdx.y;
    const float* Wb = qv ? Wb_v : Wb_q;
    __half* oh = qv ? g_wbtv : g_wbtq;
    int i = blockIdx.x * 256 + threadIdx.x;   // DIM*KP = 24576
    int n = i >> 5, k = i & 31;
    oh[i] = __float2half_rn((k < RR) ? Wb[k * DIM + n] : 0.f);
}

// ---------------------------------------------------------------------------
// mid = conv3x3 + b3 + conv1x1 + b1 + identity; output fp16, K padded to 32
// ---------------------------------------------------------------------------
__global__ void k_conv(const float* __restrict__ K_q3, const float* __restrict__ b_q3,
                       const float* __restrict__ K_v3, const float* __restrict__ b_v3,
                       const float* __restrict__ K_q1, const float* __restrict__ b_q1,
                       const float* __restrict__ K_v1, const float* __restrict__ b_v1) {
    __shared__ float sh[18 * 18 * 17];
    __shared__ float sK3[9 * RR * RR];
    __shared__ float sK1[RR * RR];
    __shared__ float sb[RR];

    const int qv = blockIdx.z;
    const float* __restrict__ a  = qv == 0 ? g_aq : g_av;
    const float* __restrict__ K3 = qv == 0 ? K_q3 : K_v3;
    const float* __restrict__ K1 = qv == 0 ? K_q1 : K_v1;
    const float* __restrict__ b3 = qv == 0 ? b_q3 : b_v3;
    const float* __restrict__ b1 = qv == 0 ? b_q1 : b_v1;
    __half* __restrict__ mh = qv == 0 ? g_mqh : g_mvh;

    const int tile_x = blockIdx.x * 16;
    const int img    = blockIdx.y >> 2;
    const int tile_y = (blockIdx.y & 3) * 16;
    const int tid = threadIdx.x;

    for (int i = tid; i < 9 * RR * RR; i += 256) sK3[i] = K3[i];
    for (int i = tid; i < RR * RR; i += 256) sK1[i] = K1[i];
    if (tid < RR) sb[tid] = b3[tid] + b1[tid];

    for (int i = tid; i < 18 * 18 * 16; i += 256) {
        int c = i & 15;
        int p = i >> 4;
        int ww = p % 18, hh = p / 18;
        int h = tile_y + hh - 1, w = tile_x + ww - 1;
        float v = 0.f;
        if (h >= 0 && h < HH && w >= 0 && w < WW)
            v = a[(((img * HH + h) * WW) + w) * RR + c];
        sh[(hh * 18 + ww) * 17 + c] = v;
    }
    __syncthreads();

    const int ty = tid >> 4, tx = tid & 15;
    float acc[RR];
    const float* center = &sh[((ty + 1) * 18 + (tx + 1)) * 17];
    #pragma unroll
    for (int co = 0; co < RR; co++) acc[co] = sb[co] + center[co];

    #pragma unroll
    for (int ci = 0; ci < RR; ci++) {
        float v = center[ci];
        #pragma unroll
        for (int co = 0; co < RR; co++) acc[co] += v * sK1[ci * RR + co];
    }
    #pragma unroll
    for (int kh = 0; kh < 3; kh++) {
        #pragma unroll
        for (int kw = 0; kw < 3; kw++) {
            const float* p  = &sh[((ty + kh) * 18 + (tx + kw)) * 17];
            const float* kk = &sK3[(kh * 3 + kw) * RR * RR];
            #pragma unroll
            for (int ci = 0; ci < RR; ci++) {
                float v = p[ci];
                #pragma unroll
                for (int co = 0; co < RR; co++) acc[co] += v * kk[ci * RR + co];
            }
        }
    }

    const int h = tile_y + ty, w = tile_x + tx;
    const int pix = ((img * HH + h) * WW) + w;
    __half hb[RR];
    #pragma unroll
    for (int co = 0; co < RR; co++) hb[co] = __float2half_rn(acc[co]);
    uint4* oh = (uint4*)(mh + (size_t)pix * KP);
    oh[0] = ((uint4*)hb)[0];
    oh[1] = ((uint4*)hb)[1];
    uint4 z = make_uint4(0, 0, 0, 0);
    oh[2] = z;
    oh[3] = z;
}

// ---------------------------------------------------------------------------
// Main HMMA GEMM (round-4 proven config): 128x128 CTA tile, 64x32 warp tiles,
// BK=32, 4-stage cp.async pipeline, fused LoRA chunk + bias epilogue.
// ---------------------------------------------------------------------------
__global__ void __launch_bounds__(256) k_mma(const float* __restrict__ bqkv,
                                             float* __restrict__ out) {
    extern __shared__ char smem[];
    const uint32_t sbase = smem_u32(smem);
    const int tid = threadIdx.x;
    const int wid = tid >> 5, lane = tid & 31;
    const int wm = (wid & 1) * 64;
    const int wn = (wid >> 1) * 32;
    const int grp = lane >> 2, tig = lane & 3;

    const int n0 = blockIdx.x * 128;
    const int m0 = blockIdx.y * 128;
    const int region = (n0 < DIM) ? 0 : (n0 >= 2 * DIM ? 1 : -1);
    const int nr = n0 - (region == 1 ? 2 * DIM : 0);
    const int total = (region >= 0) ? 25 : 24;

    const int l_row0 = tid >> 2,         l_c0 = (tid & 3);
    const int l_row1 = (tid + 256) >> 2, l_c1 = ((tid + 256) & 3);

    float acc[4][4][4];
    #pragma unroll
    for (int i = 0; i < 4; i++)
        #pragma unroll
        for (int j = 0; j < 4; j++)
            #pragma unroll
            for (int k = 0; k < 4; k++) acc[i][j][k] = 0.f;

    auto job = [&](int idx, const __half*& A, const __half*& B, int& rsa, int& rsb) {
        if (idx < 24) {
            A = g_xh + (size_t)m0 * DIM + idx * 32;
            B = g_wth + (size_t)n0 * DIM + idx * 32;
            rsa = DIM; rsb = DIM;
        } else {
            A = (region == 0 ? g_mqh : g_mvh) + (size_t)m0 * KP;
            B = (region == 0 ? g_wbtq : g_wbtv) + (size_t)nr * KP;
            rsa = KP; rsb = KP;
        }
    };

    auto load_chunk = [&](int idx) {
        const __half *A, *B;
        int rsa, rsb;
        job(idx, A, B, rsa, rsb);
        const uint32_t sa = sbase + (uint32_t)(idx & (STAGES - 1)) * STAGE_BYTES;
        const uint32_t sb = sa + STAGE_A_BYTES;
        cp16(sa + (uint32_t)(l_row0 * 80 + l_c0 * 16), A + (size_t)l_row0 * rsa + l_c0 * 8);
        cp16(sa + (uint32_t)(l_row1 * 80 + l_c1 * 16), A + (size_t)l_row1 * rsa + l_c1 * 8);
        cp16(sb + (uint32_t)(l_row0 * 80 + l_c0 * 16), B + (size_t)l_row0 * rsb + l_c0 * 8);
        cp16(sb + (uint32_t)(l_row1 * 80 + l_c1 * 16), B + (size_t)l_row1 * rsb + l_c1 * 8);
        asm volatile("cp.async.commit_group;");
    };

    #pragma unroll
    for (int s = 0; s < STAGES - 1; s++) load_chunk(s);

    const uint32_t a_row = (uint32_t)(wm + (lane & 15));
    const uint32_t a_kof = (uint32_t)((lane >> 4) * 8);
    const uint32_t b_row = (uint32_t)(wn + (lane & 7) + ((lane >> 4) * 8));
    const uint32_t b_kof = (uint32_t)(((lane >> 3) & 1) * 8);

    for (int i = 0; i < total; i++) {
        asm volatile("cp.async.wait_group %0;" :: "n"(STAGES - 2));
        __syncthreads();
        if (i + STAGES - 1 < total) load_chunk(i + STAGES - 1);

        const uint32_t aBase = sbase + (uint32_t)(i & (STAGES - 1)) * STAGE_BYTES;
        const uint32_t bBase = aBase + STAGE_A_BYTES;

        #pragma unroll
        for (int ks = 0; ks < 2; ks++) {
            uint32_t a[4][4], b[4][2];
            #pragma unroll
            for (int mi = 0; mi < 4; mi++) {
                uint32_t ad = aBase + ((a_row + mi * 16) * APITCH + ks * 16 + a_kof) * 2;
                ldm_x4(ad, a[mi][0], a[mi][1], a[mi][2], a[mi][3]);
            }
            #pragma unroll
            for (int nj = 0; nj < 2; nj++) {
                uint32_t bd = bBase + ((b_row + nj * 16) * APITCH + ks * 16 + b_kof) * 2;
                ldm_x4(bd, b[nj * 2][0], b[nj * 2][1], b[nj * 2 + 1][0], b[nj * 2 + 1][1]);
            }
            #pragma unroll
            for (int mi = 0; mi < 4; mi++)
                #pragma unroll
                for (int ni = 0; ni < 4; ni++)
                    mma16816(acc[mi][ni], a[mi], b[ni]);
        }
    }

    #pragma unroll
    for (int ni = 0; ni < 4; ni++) {
        const int n = n0 + wn + ni * 8 + 2 * tig;
        const float2 bv = *(const float2*)&bqkv[n];
        #pragma unroll
        for (int mi = 0; mi < 4; mi++) {
            const int m = m0 + wm + mi * 16 + grp;
            float2 v0 = make_float2(acc[mi][ni][0] + bv.x, acc[mi][ni][1] + bv.y);
            float2 v1 = make_float2(acc[mi][ni][2] + bv.x, acc[mi][ni][3] + bv.y);
            *(float2*)&out[(size_t)m * MOUT + n] = v0;
            *(float2*)&out[(size_t)(m + 8) * MOUT + n] = v1;
        }
    }
}

// ---------------------------------------------------------------------------
extern "C" void kernel_launch(void* const* d_in, const int* in_sizes, int n_in,
                              void* d_out, int out_size) {
    const float* x     = (const float*)d_in[0];
    const float* W_qkv = (const float*)d_in[1];
    const float* b_qkv = (const float*)d_in[2];
    const float* Wa_q  = (const float*)d_in[3];
    const float* Wb_q  = (const float*)d_in[4];
    const float* Wa_v  = (const float*)d_in[5];
    const float* Wb_v  = (const float*)d_in[6];
    const float* K_q3  = (const float*)d_in[7];
    const float* b_q3  = (const float*)d_in[8];
    const float* K_v3  = (const float*)d_in[9];
    const float* b_v3  = (const float*)d_in[10];
    const float* K_q1  = (const float*)d_in[11];
    const float* b_q1  = (const float*)d_in[12];
    const float* K_v1  = (const float*)d_in[13];
    const float* b_v1  = (const float*)d_in[14];
    float* out = (float*)d_out;

    cudaFuncSetAttribute(k_prep, cudaFuncAttributeMaxDynamicSharedMemorySize, SMEM_PREP);
    cudaFuncSetAttribute(k_mma, cudaFuncAttributeMaxDynamicSharedMemorySize, SMEM_MMA);

    k_prep<<<NPIX / 64, 256, SMEM_PREP>>>(x, Wa_q, Wa_v);
    k_wt<<<dim3(MOUT / 32, DIM / 32), 256>>>(W_qkv);
    k_wbt<<<dim3(DIM * KP / 256, 2), 256>>>(Wb_q, Wb_v);
    k_conv<<<dim3(WW / 16, (HH / 16) * NB, 2), 256>>>(K_q3, b_q3, K_v3, b_v3,
                                                      K_q1, b_q1, K_v1, b_v1);
    k_mma<<<dim3(MOUT / 128, NPIX / 128), 256, SMEM_MMA>>>(b_qkv, out);
}

// round 11
// speedup vs baseline: 1.0741x; 1.0741x over previous
#include <cuda_runtime.h>
#include <cuda_fp16.h>
#include <cstdint>

#define NB 8
#define HH 64
#define WW 64
#define DIM 768
#define RR 16
#define NPIX 32768
#define MOUT 2304
#define KP 32

#define STAGES 4
#define APITCH 40                         // halves per smem row (32 data + 8 pad)
#define STAGE_A_BYTES (128 * APITCH * 2)  // 10240
#define STAGE_BYTES (2 * STAGE_A_BYTES)   // 20480
#define SMEM_MMA (STAGES * STAGE_BYTES)   // 81920

#define WPITCH 776                        // k_front W smem pitch (768 + 8)
#define SW_BYTES (32 * WPITCH * 2)        // 49664
#define SX_OFF SW_BYTES
#define SMEM_FRONT (SW_BYTES + 128 * APITCH * 2)  // 59904

// block-range dispatch for k_front
#define PREP_BLOCKS 256
#define WT_BLOCKS (72 * 24)               // 1728
#define WBT_BLOCKS 192
#define FRONT_BLOCKS (PREP_BLOCKS + WT_BLOCKS + WBT_BLOCKS)  // 2176

// ------------------------- scratch (device globals) -------------------------
__device__ __align__(256) __half g_xh[NPIX * DIM];    // x in fp16
__device__ __align__(256) __half g_wth[MOUT * DIM];   // W_qkv^T fp16 [n][k]
__device__ __align__(256) float  g_aq[NPIX * RR];
__device__ __align__(256) float  g_av[NPIX * RR];
__device__ __align__(256) __half g_mqh[NPIX * KP];    // mid_q fp16, K padded 16->32
__device__ __align__(256) __half g_mvh[NPIX * KP];
__device__ __align__(256) __half g_wbtq[DIM * KP];    // Wb_q^T fp16 padded [n][k]
__device__ __align__(256) __half g_wbtv[DIM * KP];

// ------------------------------ helpers -------------------------------------
__device__ __forceinline__ uint32_t smem_u32(const void* p) {
    uint32_t a;
    asm("{ .reg .u64 t; cvta.to.shared.u64 t, %1; cvt.u32.u64 %0, t; }" : "=r"(a) : "l"(p));
    return a;
}

__device__ __forceinline__ void cp16(uint32_t dst, const void* src) {
    asm volatile("cp.async.cg.shared.global [%0], [%1], 16;" :: "r"(dst), "l"(src));
}

__device__ __forceinline__ void ldm_x4(uint32_t addr, uint32_t& r0, uint32_t& r1,
                                       uint32_t& r2, uint32_t& r3) {
    asm volatile("ldmatrix.sync.aligned.m8n8.x4.shared.b16 {%0,%1,%2,%3}, [%4];"
                 : "=r"(r0), "=r"(r1), "=r"(r2), "=r"(r3) : "r"(addr));
}

__device__ __forceinline__ void mma16816(float* c, const uint32_t* a, const uint32_t* b) {
    asm volatile(
        "mma.sync.aligned.m16n8k16.row.col.f32.f16.f16.f32 "
        "{%0,%1,%2,%3}, {%4,%5,%6,%7}, {%8,%9}, {%0,%1,%2,%3};"
        : "+f"(c[0]), "+f"(c[1]), "+f"(c[2]), "+f"(c[3])
        : "r"(a[0]), "r"(a[1]), "r"(a[2]), "r"(a[3]), "r"(b[0]), "r"(b[1]));
}

// ---------------------------------------------------------------------------
// k_front: fused front-end, block-range dispatch.
//  blocks [0,256):      prep -- x->fp16 (g_xh) + a_q|a_v = x @ [Wa_q|Wa_v] (HMMA)
//  blocks [256,1984):   W_qkv transpose+convert -> g_wth
//  blocks [1984,2176):  Wb transpose+pad+convert -> g_wbtq/g_wbtv
// ---------------------------------------------------------------------------
__global__ void __launch_bounds__(256, 2) k_front(
    const float* __restrict__ x,
    const float* __restrict__ Wa_q, const float* __restrict__ Wa_v,
    const float* __restrict__ W,
    const float* __restrict__ Wb_q, const float* __restrict__ Wb_v) {
    extern __shared__ char sm[];
    const int tid = threadIdx.x;
    const int bid = blockIdx.x;

    if (bid >= PREP_BLOCKS + WT_BLOCKS) {
        // ---- wbt: Wb [16][768] -> transposed padded fp16 [768][32] ----
        const int b = bid - (PREP_BLOCKS + WT_BLOCKS);
        const int qv = b >= 96;
        const float* Wb = qv ? Wb_v : Wb_q;
        __half* oh = qv ? g_wbtv : g_wbtq;
        int i = (b - (qv ? 96 : 0)) * 256 + tid;   // over DIM*KP = 24576
        int n = i >> 5, k = i & 31;
        oh[i] = __float2half_rn((k < RR) ? Wb[k * DIM + n] : 0.f);
        return;
    }

    if (bid >= PREP_BLOCKS) {
        // ---- wt: W_qkv [768][2304] -> transposed fp16 [2304][768] ----
        float (*t)[33] = (float(*)[33])sm;
        const int b = bid - PREP_BLOCKS;
        const int bx = b % 72;             // MOUT/32
        const int by = b / 72;             // DIM/32
        const int tx = tid & 31, ty = tid >> 5;
        #pragma unroll
        for (int k = 0; k < 4; k++) {
            int r = by * 32 + ty + k * 8;
            t[ty + k * 8][tx] = W[(size_t)r * MOUT + bx * 32 + tx];
        }
        __syncthreads();
        #pragma unroll
        for (int k = 0; k < 4; k++) {
            int n = bx * 32 + ty + k * 8;
            g_wth[(size_t)n * DIM + by * 32 + tx] = __float2half_rn(t[tx][ty + k * 8]);
        }
        return;
    }

    // ---- prep ----
    __half* sW = (__half*)sm;              // [n=32][k=768] pitch WPITCH
    __half* sX = (__half*)(sm + SX_OFF);   // [128][32] pitch APITCH
    const uint32_t sbase = smem_u32(sm);
    const int wid = tid >> 5, lane = tid & 31;
    const int m0 = bid * 128;

    for (int i = tid; i < DIM * 32; i += 256) {
        int k = i >> 5, n = i & 31;
        float v = (n < 16) ? Wa_q[k * RR + n] : Wa_v[k * RR + (n - 16)];
        sW[n * WPITCH + k] = __float2half_rn(v);
    }

    const int row = tid >> 1;
    const int hs = tid & 1;
    const float* src = x + (size_t)(m0 + row) * DIM + hs * 16;
    __half* gxr = g_xh + (size_t)(m0 + row) * DIM + hs * 16;
    __half* sxr = sX + row * APITCH + hs * 16;

    float acc[4][4];
    #pragma unroll
    for (int i = 0; i < 4; i++)
        #pragma unroll
        for (int j = 0; j < 4; j++) acc[i][j] = 0.f;

    const uint32_t a_row = (uint32_t)(wid * 16 + (lane & 15));
    const uint32_t a_k8  = (uint32_t)((lane >> 4) * 8);
    const uint32_t b_row = (uint32_t)((lane & 7) + ((lane >> 4) * 8));
    const uint32_t b_k8  = (uint32_t)(((lane >> 3) & 1) * 8);

    // prefetch chunk 0
    float4 f0 = *(const float4*)(src);
    float4 f1 = *(const float4*)(src + 4);
    float4 f2 = *(const float4*)(src + 8);
    float4 f3 = *(const float4*)(src + 12);

    for (int kb = 0; kb < 24; kb++) {
        // prefetch next chunk into registers (hidden under this chunk's MMA)
        float4 p0, p1, p2, p3;
        if (kb < 23) {
            const float* nsrc = src + (kb + 1) * 32;
            p0 = *(const float4*)(nsrc);
            p1 = *(const float4*)(nsrc + 4);
            p2 = *(const float4*)(nsrc + 8);
            p3 = *(const float4*)(nsrc + 12);
        }

        __half h[16];
        h[0] = __float2half_rn(f0.x);  h[1] = __float2half_rn(f0.y);
        h[2] = __float2half_rn(f0.z);  h[3] = __float2half_rn(f0.w);
        h[4] = __float2half_rn(f1.x);  h[5] = __float2half_rn(f1.y);
        h[6] = __float2half_rn(f1.z);  h[7] = __float2half_rn(f1.w);
        h[8] = __float2half_rn(f2.x);  h[9] = __float2half_rn(f2.y);
        h[10] = __float2half_rn(f2.z); h[11] = __float2half_rn(f2.w);
        h[12] = __float2half_rn(f3.x); h[13] = __float2half_rn(f3.y);
        h[14] = __float2half_rn(f3.z); h[15] = __float2half_rn(f3.w);

        *(uint4*)(gxr + kb * 32) = ((uint4*)h)[0];
        *(uint4*)(gxr + kb * 32 + 8) = ((uint4*)h)[1];
        *(uint4*)sxr = ((uint4*)h)[0];
        *(uint4*)(sxr + 8) = ((uint4*)h)[1];
        __syncthreads();

        #pragma unroll
        for (int ks = 0; ks < 2; ks++) {
            uint32_t a[4];
            uint32_t ad = sbase + SX_OFF + (a_row * APITCH + ks * 16 + a_k8) * 2;
            ldm_x4(ad, a[0], a[1], a[2], a[3]);
            uint32_t b[4][2];
            #pragma unroll
            for (int nj = 0; nj < 2; nj++) {
                uint32_t bd = sbase +
                    ((b_row + nj * 16) * WPITCH + kb * 32 + ks * 16 + b_k8) * 2;
                ldm_x4(bd, b[nj * 2][0], b[nj * 2][1],
                       b[nj * 2 + 1][0], b[nj * 2 + 1][1]);
            }
            #pragma unroll
            for (int nj = 0; nj < 4; nj++) mma16816(acc[nj], a, b[nj]);
        }
        __syncthreads();

        f0 = p0; f1 = p1; f2 = p2; f3 = p3;
    }

    const int grp = lane >> 2, tig = lane & 3;
    const int r0 = m0 + wid * 16 + grp;
    #pragma unroll
    for (int nj = 0; nj < 4; nj++) {
        int n = nj * 8 + 2 * tig;
        float* o = (n < 16) ? g_aq : g_av;
        int nn = n & 15;
        *(float2*)&o[(size_t)r0 * RR + nn] = make_float2(acc[nj][0], acc[nj][1]);
        *(float2*)&o[(size_t)(r0 + 8) * RR + nn] = make_float2(acc[nj][2], acc[nj][3]);
    }
}

// ---------------------------------------------------------------------------
// mid = conv3x3 + b3 + conv1x1 + b1 + identity; output fp16, K padded to 32
// ---------------------------------------------------------------------------
__global__ void k_conv(const float* __restrict__ K_q3, const float* __restrict__ b_q3,
                       const float* __restrict__ K_v3, const float* __restrict__ b_v3,
                       const float* __restrict__ K_q1, const float* __restrict__ b_q1,
                       const float* __restrict__ K_v1, const float* __restrict__ b_v1) {
    __shared__ float sh[18 * 18 * 17];
    __shared__ float sK3[9 * RR * RR];
    __shared__ float sK1[RR * RR];
    __shared__ float sb[RR];

    const int qv = blockIdx.z;
    const float* __restrict__ a  = qv == 0 ? g_aq : g_av;
    const float* __restrict__ K3 = qv == 0 ? K_q3 : K_v3;
    const float* __restrict__ K1 = qv == 0 ? K_q1 : K_v1;
    const float* __restrict__ b3 = qv == 0 ? b_q3 : b_v3;
    const float* __restrict__ b1 = qv == 0 ? b_q1 : b_v1;
    __half* __restrict__ mh = qv == 0 ? g_mqh : g_mvh;

    const int tile_x = blockIdx.x * 16;
    const int img    = blockIdx.y >> 2;
    const int tile_y = (blockIdx.y & 3) * 16;
    const int tid = threadIdx.x;

    for (int i = tid; i < 9 * RR * RR; i += 256) sK3[i] = K3[i];
    for (int i = tid; i < RR * RR; i += 256) sK1[i] = K1[i];
    if (tid < RR) sb[tid] = b3[tid] + b1[tid];

    for (int i = tid; i < 18 * 18 * 16; i += 256) {
        int c = i & 15;
        int p = i >> 4;
        int ww = p % 18, hh = p / 18;
        int h = tile_y + hh - 1, w = tile_x + ww - 1;
        float v = 0.f;
        if (h >= 0 && h < HH && w >= 0 && w < WW)
            v = a[(((img * HH + h) * WW) + w) * RR + c];
        sh[(hh * 18 + ww) * 17 + c] = v;
    }
    __syncthreads();

    const int ty = tid >> 4, tx = tid & 15;
    float acc[RR];
    const float* center = &sh[((ty + 1) * 18 + (tx + 1)) * 17];
    #pragma unroll
    for (int co = 0; co < RR; co++) acc[co] = sb[co] + center[co];

    #pragma unroll
    for (int ci = 0; ci < RR; ci++) {
        float v = center[ci];
        #pragma unroll
        for (int co = 0; co < RR; co++) acc[co] += v * sK1[ci * RR + co];
    }
    #pragma unroll
    for (int kh = 0; kh < 3; kh++) {
        #pragma unroll
        for (int kw = 0; kw < 3; kw++) {
            const float* p  = &sh[((ty + kh) * 18 + (tx + kw)) * 17];
            const float* kk = &sK3[(kh * 3 + kw) * RR * RR];
            #pragma unroll
            for (int ci = 0; ci < RR; ci++) {
                float v = p[ci];
                #pragma unroll
                for (int co = 0; co < RR; co++) acc[co] += v * kk[ci * RR + co];
            }
        }
    }

    const int h = tile_y + ty, w = tile_x + tx;
    const int pix = ((img * HH + h) * WW) + w;
    __half hb[RR];
    #pragma unroll
    for (int co = 0; co < RR; co++) hb[co] = __float2half_rn(acc[co]);
    uint4* oh = (uint4*)(mh + (size_t)pix * KP);
    oh[0] = ((uint4*)hb)[0];
    oh[1] = ((uint4*)hb)[1];
    uint4 z = make_uint4(0, 0, 0, 0);
    oh[2] = z;
    oh[3] = z;
}

// ---------------------------------------------------------------------------
// Main HMMA GEMM (round-4 proven config): 128x128 CTA tile, 64x32 warp tiles,
// BK=32, 4-stage cp.async pipeline, fused LoRA chunk + bias epilogue.
// ---------------------------------------------------------------------------
__global__ void __launch_bounds__(256) k_mma(const float* __restrict__ bqkv,
                                             float* __restrict__ out) {
    extern __shared__ char smem[];
    const uint32_t sbase = smem_u32(smem);
    const int tid = threadIdx.x;
    const int wid = tid >> 5, lane = tid & 31;
    const int wm = (wid & 1) * 64;
    const int wn = (wid >> 1) * 32;
    const int grp = lane >> 2, tig = lane & 3;

    const int n0 = blockIdx.x * 128;
    const int m0 = blockIdx.y * 128;
    const int region = (n0 < DIM) ? 0 : (n0 >= 2 * DIM ? 1 : -1);
    const int nr = n0 - (region == 1 ? 2 * DIM : 0);
    const int total = (region >= 0) ? 25 : 24;

    const int l_row0 = tid >> 2,         l_c0 = (tid & 3);
    const int l_row1 = (tid + 256) >> 2, l_c1 = ((tid + 256) & 3);

    float acc[4][4][4];
    #pragma unroll
    for (int i = 0; i < 4; i++)
        #pragma unroll
        for (int j = 0; j < 4; j++)
            #pragma unroll
            for (int k = 0; k < 4; k++) acc[i][j][k] = 0.f;

    auto job = [&](int idx, const __half*& A, const __half*& B, int& rsa, int& rsb) {
        if (idx < 24) {
            A = g_xh + (size_t)m0 * DIM + idx * 32;
            B = g_wth + (size_t)n0 * DIM + idx * 32;
            rsa = DIM; rsb = DIM;
        } else {
            A = (region == 0 ? g_mqh : g_mvh) + (size_t)m0 * KP;
            B = (region == 0 ? g_wbtq : g_wbtv) + (size_t)nr * KP;
            rsa = KP; rsb = KP;
        }
    };

    auto load_chunk = [&](int idx) {
        const __half *A, *B;
        int rsa, rsb;
        job(idx, A, B, rsa, rsb);
        const uint32_t sa = sbase + (uint32_t)(idx & (STAGES - 1)) * STAGE_BYTES;
        const uint32_t sb = sa + STAGE_A_BYTES;
        cp16(sa + (uint32_t)(l_row0 * 80 + l_c0 * 16), A + (size_t)l_row0 * rsa + l_c0 * 8);
        cp16(sa + (uint32_t)(l_row1 * 80 + l_c1 * 16), A + (size_t)l_row1 * rsa + l_c1 * 8);
        cp16(sb + (uint32_t)(l_row0 * 80 + l_c0 * 16), B + (size_t)l_row0 * rsb + l_c0 * 8);
        cp16(sb + (uint32_t)(l_row1 * 80 + l_c1 * 16), B + (size_t)l_row1 * rsb + l_c1 * 8);
        asm volatile("cp.async.commit_group;");
    };

    #pragma unroll
    for (int s = 0; s < STAGES - 1; s++) load_chunk(s);

    const uint32_t a_row = (uint32_t)(wm + (lane & 15));
    const uint32_t a_kof = (uint32_t)((lane >> 4) * 8);
    const uint32_t b_row = (uint32_t)(wn + (lane & 7) + ((lane >> 4) * 8));
    const uint32_t b_kof = (uint32_t)(((lane >> 3) & 1) * 8);

    for (int i = 0; i < total; i++) {
        asm volatile("cp.async.wait_group %0;" :: "n"(STAGES - 2));
        __syncthreads();
        if (i + STAGES - 1 < total) load_chunk(i + STAGES - 1);

        const uint32_t aBase = sbase + (uint32_t)(i & (STAGES - 1)) * STAGE_BYTES;
        const uint32_t bBase = aBase + STAGE_A_BYTES;

        #pragma unroll
        for (int ks = 0; ks < 2; ks++) {
            uint32_t a[4][4], b[4][2];
            #pragma unroll
            for (int mi = 0; mi < 4; mi++) {
                uint32_t ad = aBase + ((a_row + mi * 16) * APITCH + ks * 16 + a_kof) * 2;
                ldm_x4(ad, a[mi][0], a[mi][1], a[mi][2], a[mi][3]);
            }
            #pragma unroll
            for (int nj = 0; nj < 2; nj++) {
                uint32_t bd = bBase + ((b_row + nj * 16) * APITCH + ks * 16 + b_kof) * 2;
                ldm_x4(bd, b[nj * 2][0], b[nj * 2][1], b[nj * 2 + 1][0], b[nj * 2 + 1][1]);
            }
            #pragma unroll
            for (int mi = 0; mi < 4; mi++)
                #pragma unroll
                for (int ni = 0; ni < 4; ni++)
                    mma16816(acc[mi][ni], a[mi], b[ni]);
        }
    }

    #pragma unroll
    for (int ni = 0; ni < 4; ni++) {
        const int n = n0 + wn + ni * 8 + 2 * tig;
        const float2 bv = *(const float2*)&bqkv[n];
        #pragma unroll
        for (int mi = 0; mi < 4; mi++) {
            const int m = m0 + wm + mi * 16 + grp;
            float2 v0 = make_float2(acc[mi][ni][0] + bv.x, acc[mi][ni][1] + bv.y);
            float2 v1 = make_float2(acc[mi][ni][2] + bv.x, acc[mi][ni][3] + bv.y);
            *(float2*)&out[(size_t)m * MOUT + n] = v0;
            *(float2*)&out[(size_t)(m + 8) * MOUT + n] = v1;
        }
    }
}

// ---------------------------------------------------------------------------
extern "C" void kernel_launch(void* const* d_in, const int* in_sizes, int n_in,
                              void* d_out, int out_size) {
    const float* x     = (const float*)d_in[0];
    const float* W_qkv = (const float*)d_in[1];
    const float* b_qkv = (const float*)d_in[2];
    const float* Wa_q  = (const float*)d_in[3];
    const float* Wb_q  = (const float*)d_in[4];
    const float* Wa_v  = (const float*)d_in[5];
    const float* Wb_v  = (const float*)d_in[6];
    const float* K_q3  = (const float*)d_in[7];
    const float* b_q3  = (const float*)d_in[8];
    const float* K_v3  = (const float*)d_in[9];
    const float* b_v3  = (const float*)d_in[10];
    const float* K_q1  = (const float*)d_in[11];
    const float* b_q1  = (const float*)d_in[12];
    const float* K_v1  = (const float*)d_in[13];
    const float* b_v1  = (const float*)d_in[14];
    float* out = (float*)d_out;

    cudaFuncSetAttribute(k_front, cudaFuncAttributeMaxDynamicSharedMemorySize, SMEM_FRONT);
    cudaFuncSetAttribute(k_mma, cudaFuncAttributeMaxDynamicSharedMemorySize, SMEM_MMA);

    k_front<<<FRONT_BLOCKS, 256, SMEM_FRONT>>>(x, Wa_q, Wa_v, W_qkv, Wb_q, Wb_v);
    k_conv<<<dim3(WW / 16, (HH / 16) * NB, 2), 256>>>(K_q3, b_q3, K_v3, b_v3,
                                                      K_q1, b_q1, K_v1, b_v1);
    k_mma<<<dim3(MOUT / 128, NPIX / 128), 256, SMEM_MMA>>>(b_qkv, out);
}

// round 12
// speedup vs baseline: 1.1759x; 1.0948x over previous
#include <cuda_runtime.h>
#include <cuda_fp16.h>
#include <cstdint>

#define NB 8
#define HH 64
#define WW 64
#define DIM 768
#define RR 16
#define NPIX 32768
#define MOUT 2304
#define KP 64

#define STAGES 3
#define BK 64
#define APITCH 72                         // halves per smem row (64 data + 8 pad)
#define STAGE_A_BYTES (128 * APITCH * 2)  // 18432
#define STAGE_BYTES (2 * STAGE_A_BYTES)   // 36864
#define SMEM_MMA (STAGES * STAGE_BYTES)   // 110592

#define WPITCH 776                        // k_front W smem pitch (768 + 8)
#define SW_BYTES (32 * WPITCH * 2)        // 49664
#define SX_OFF SW_BYTES
#define FAPITCH 40
#define SMEM_FRONT (SW_BYTES + 128 * FAPITCH * 2)  // 59904

// block-range dispatch for k_front
#define PREP_BLOCKS 256
#define WT_BLOCKS (72 * 24)               // 1728
#define WBT_BLOCKS 384                    // 2 * DIM*KP/256
#define FRONT_BLOCKS (PREP_BLOCKS + WT_BLOCKS + WBT_BLOCKS)  // 2368

// ------------------------- scratch (device globals) -------------------------
__device__ __align__(256) __half g_xh[NPIX * DIM];    // x in fp16
__device__ __align__(256) __half g_wth[MOUT * DIM];   // W_qkv^T fp16 [n][k]
__device__ __align__(256) float  g_aq[NPIX * RR];
__device__ __align__(256) float  g_av[NPIX * RR];
__device__ __align__(256) __half g_mqh[NPIX * KP];    // mid_q fp16, K padded 16->64
__device__ __align__(256) __half g_mvh[NPIX * KP];
__device__ __align__(256) __half g_wbtq[DIM * KP];    // Wb_q^T fp16 padded [n][k]
__device__ __align__(256) __half g_wbtv[DIM * KP];

// ------------------------------ helpers -------------------------------------
__device__ __forceinline__ uint32_t smem_u32(const void* p) {
    uint32_t a;
    asm("{ .reg .u64 t; cvta.to.shared.u64 t, %1; cvt.u32.u64 %0, t; }" : "=r"(a) : "l"(p));
    return a;
}

__device__ __forceinline__ void cp16(uint32_t dst, const void* src) {
    asm volatile("cp.async.cg.shared.global [%0], [%1], 16;" :: "r"(dst), "l"(src));
}

__device__ __forceinline__ void ldm_x4(uint32_t addr, uint32_t& r0, uint32_t& r1,
                                       uint32_t& r2, uint32_t& r3) {
    asm volatile("ldmatrix.sync.aligned.m8n8.x4.shared.b16 {%0,%1,%2,%3}, [%4];"
                 : "=r"(r0), "=r"(r1), "=r"(r2), "=r"(r3) : "r"(addr));
}

__device__ __forceinline__ void mma16816(float* c, const uint32_t* a, const uint32_t* b) {
    asm volatile(
        "mma.sync.aligned.m16n8k16.row.col.f32.f16.f16.f32 "
        "{%0,%1,%2,%3}, {%4,%5,%6,%7}, {%8,%9}, {%0,%1,%2,%3};"
        : "+f"(c[0]), "+f"(c[1]), "+f"(c[2]), "+f"(c[3])
        : "r"(a[0]), "r"(a[1]), "r"(a[2]), "r"(a[3]), "r"(b[0]), "r"(b[1]));
}

// ---------------------------------------------------------------------------
// k_front: fused front-end, block-range dispatch.
//  blocks [0,256):      prep -- x->fp16 (g_xh) + a_q|a_v = x @ [Wa_q|Wa_v] (HMMA)
//  blocks [256,1984):   W_qkv transpose+convert -> g_wth
//  blocks [1984,2368):  Wb transpose+pad(64)+convert -> g_wbtq/g_wbtv
// ---------------------------------------------------------------------------
__global__ void __launch_bounds__(256, 2) k_front(
    const float* __restrict__ x,
    const float* __restrict__ Wa_q, const float* __restrict__ Wa_v,
    const float* __restrict__ W,
    const float* __restrict__ Wb_q, const float* __restrict__ Wb_v) {
    extern __shared__ char sm[];
    const int tid = threadIdx.x;
    const int bid = blockIdx.x;

    if (bid >= PREP_BLOCKS + WT_BLOCKS) {
        // ---- wbt: Wb [16][768] -> transposed padded fp16 [768][64] ----
        const int b = bid - (PREP_BLOCKS + WT_BLOCKS);
        const int qv = b >= 192;
        const float* Wb = qv ? Wb_v : Wb_q;
        __half* oh = qv ? g_wbtv : g_wbtq;
        int i = (b - (qv ? 192 : 0)) * 256 + tid;   // over DIM*KP = 49152
        int n = i >> 6, k = i & 63;
        oh[i] = __float2half_rn((k < RR) ? Wb[k * DIM + n] : 0.f);
        return;
    }

    if (bid >= PREP_BLOCKS) {
        // ---- wt: W_qkv [768][2304] -> transposed fp16 [2304][768] ----
        float (*t)[33] = (float(*)[33])sm;
        const int b = bid - PREP_BLOCKS;
        const int bx = b % 72;             // MOUT/32
        const int by = b / 72;             // DIM/32
        const int tx = tid & 31, ty = tid >> 5;
        #pragma unroll
        for (int k = 0; k < 4; k++) {
            int r = by * 32 + ty + k * 8;
            t[ty + k * 8][tx] = W[(size_t)r * MOUT + bx * 32 + tx];
        }
        __syncthreads();
        #pragma unroll
        for (int k = 0; k < 4; k++) {
            int n = bx * 32 + ty + k * 8;
            g_wth[(size_t)n * DIM + by * 32 + tx] = __float2half_rn(t[tx][ty + k * 8]);
        }
        return;
    }

    // ---- prep ----
    __half* sW = (__half*)sm;              // [n=32][k=768] pitch WPITCH
    __half* sX = (__half*)(sm + SX_OFF);   // [128][32] pitch FAPITCH
    const uint32_t sbase = smem_u32(sm);
    const int wid = tid >> 5, lane = tid & 31;
    const int m0 = bid * 128;

    for (int i = tid; i < DIM * 32; i += 256) {
        int k = i >> 5, n = i & 31;
        float v = (n < 16) ? Wa_q[k * RR + n] : Wa_v[k * RR + (n - 16)];
        sW[n * WPITCH + k] = __float2half_rn(v);
    }

    const int row = tid >> 1;
    const int hs = tid & 1;
    const float* src = x + (size_t)(m0 + row) * DIM + hs * 16;
    __half* gxr = g_xh + (size_t)(m0 + row) * DIM + hs * 16;
    __half* sxr = sX + row * FAPITCH + hs * 16;

    float acc[4][4];
    #pragma unroll
    for (int i = 0; i < 4; i++)
        #pragma unroll
        for (int j = 0; j < 4; j++) acc[i][j] = 0.f;

    const uint32_t a_row = (uint32_t)(wid * 16 + (lane & 15));
    const uint32_t a_k8  = (uint32_t)((lane >> 4) * 8);
    const uint32_t b_row = (uint32_t)((lane & 7) + ((lane >> 4) * 8));
    const uint32_t b_k8  = (uint32_t)(((lane >> 3) & 1) * 8);

    float4 f0 = *(const float4*)(src);
    float4 f1 = *(const float4*)(src + 4);
    float4 f2 = *(const float4*)(src + 8);
    float4 f3 = *(const float4*)(src + 12);

    for (int kb = 0; kb < 24; kb++) {
        float4 p0, p1, p2, p3;
        if (kb < 23) {
            const float* nsrc = src + (kb + 1) * 32;
            p0 = *(const float4*)(nsrc);
            p1 = *(const float4*)(nsrc + 4);
            p2 = *(const float4*)(nsrc + 8);
            p3 = *(const float4*)(nsrc + 12);
        }

        __half h[16];
        h[0] = __float2half_rn(f0.x);  h[1] = __float2half_rn(f0.y);
        h[2] = __float2half_rn(f0.z);  h[3] = __float2half_rn(f0.w);
        h[4] = __float2half_rn(f1.x);  h[5] = __float2half_rn(f1.y);
        h[6] = __float2half_rn(f1.z);  h[7] = __float2half_rn(f1.w);
        h[8] = __float2half_rn(f2.x);  h[9] = __float2half_rn(f2.y);
        h[10] = __float2half_rn(f2.z); h[11] = __float2half_rn(f2.w);
        h[12] = __float2half_rn(f3.x); h[13] = __float2half_rn(f3.y);
        h[14] = __float2half_rn(f3.z); h[15] = __float2half_rn(f3.w);

        *(uint4*)(gxr + kb * 32) = ((uint4*)h)[0];
        *(uint4*)(gxr + kb * 32 + 8) = ((uint4*)h)[1];
        *(uint4*)sxr = ((uint4*)h)[0];
        *(uint4*)(sxr + 8) = ((uint4*)h)[1];
        __syncthreads();

        #pragma unroll
        for (int ks = 0; ks < 2; ks++) {
            uint32_t a[4];
            uint32_t ad = sbase + SX_OFF + (a_row * FAPITCH + ks * 16 + a_k8) * 2;
            ldm_x4(ad, a[0], a[1], a[2], a[3]);
            uint32_t b[4][2];
            #pragma unroll
            for (int nj = 0; nj < 2; nj++) {
                uint32_t bd = sbase +
                    ((b_row + nj * 16) * WPITCH + kb * 32 + ks * 16 + b_k8) * 2;
                ldm_x4(bd, b[nj * 2][0], b[nj * 2][1],
                       b[nj * 2 + 1][0], b[nj * 2 + 1][1]);
            }
            #pragma unroll
            for (int nj = 0; nj < 4; nj++) mma16816(acc[nj], a, b[nj]);
        }
        __syncthreads();

        f0 = p0; f1 = p1; f2 = p2; f3 = p3;
    }

    const int grp = lane >> 2, tig = lane & 3;
    const int r0 = m0 + wid * 16 + grp;
    #pragma unroll
    for (int nj = 0; nj < 4; nj++) {
        int n = nj * 8 + 2 * tig;
        float* o = (n < 16) ? g_aq : g_av;
        int nn = n & 15;
        *(float2*)&o[(size_t)r0 * RR + nn] = make_float2(acc[nj][0], acc[nj][1]);
        *(float2*)&o[(size_t)(r0 + 8) * RR + nn] = make_float2(acc[nj][2], acc[nj][3]);
    }
}

// ---------------------------------------------------------------------------
// mid = conv3x3 + b3 + conv1x1 + b1 + identity; output fp16, K padded to 64
// ---------------------------------------------------------------------------
__global__ void k_conv(const float* __restrict__ K_q3, const float* __restrict__ b_q3,
                       const float* __restrict__ K_v3, const float* __restrict__ b_v3,
                       const float* __restrict__ K_q1, const float* __restrict__ b_q1,
                       const float* __restrict__ K_v1, const float* __restrict__ b_v1) {
    __shared__ float sh[18 * 18 * 17];
    __shared__ float sK3[9 * RR * RR];
    __shared__ float sK1[RR * RR];
    __shared__ float sb[RR];

    const int qv = blockIdx.z;
    const float* __restrict__ a  = qv == 0 ? g_aq : g_av;
    const float* __restrict__ K3 = qv == 0 ? K_q3 : K_v3;
    const float* __restrict__ K1 = qv == 0 ? K_q1 : K_v1;
    const float* __restrict__ b3 = qv == 0 ? b_q3 : b_v3;
    const float* __restrict__ b1 = qv == 0 ? b_q1 : b_v1;
    __half* __restrict__ mh = qv == 0 ? g_mqh : g_mvh;

    const int tile_x = blockIdx.x * 16;
    const int img    = blockIdx.y >> 2;
    const int tile_y = (blockIdx.y & 3) * 16;
    const int tid = threadIdx.x;

    for (int i = tid; i < 9 * RR * RR; i += 256) sK3[i] = K3[i];
    for (int i = tid; i < RR * RR; i += 256) sK1[i] = K1[i];
    if (tid < RR) sb[tid] = b3[tid] + b1[tid];

    for (int i = tid; i < 18 * 18 * 16; i += 256) {
        int c = i & 15;
        int p = i >> 4;
        int ww = p % 18, hh = p / 18;
        int h = tile_y + hh - 1, w = tile_x + ww - 1;
        float v = 0.f;
        if (h >= 0 && h < HH && w >= 0 && w < WW)
            v = a[(((img * HH + h) * WW) + w) * RR + c];
        sh[(hh * 18 + ww) * 17 + c] = v;
    }
    __syncthreads();

    const int ty = tid >> 4, tx = tid & 15;
    float acc[RR];
    const float* center = &sh[((ty + 1) * 18 + (tx + 1)) * 17];
    #pragma unroll
    for (int co = 0; co < RR; co++) acc[co] = sb[co] + center[co];

    #pragma unroll
    for (int ci = 0; ci < RR; ci++) {
        float v = center[ci];
        #pragma unroll
        for (int co = 0; co < RR; co++) acc[co] += v * sK1[ci * RR + co];
    }
    #pragma unroll
    for (int kh = 0; kh < 3; kh++) {
        #pragma unroll
        for (int kw = 0; kw < 3; kw++) {
            const float* p  = &sh[((ty + kh) * 18 + (tx + kw)) * 17];
            const float* kk = &sK3[(kh * 3 + kw) * RR * RR];
            #pragma unroll
            for (int ci = 0; ci < RR; ci++) {
                float v = p[ci];
                #pragma unroll
                for (int co = 0; co < RR; co++) acc[co] += v * kk[ci * RR + co];
            }
        }
    }

    const int h = tile_y + ty, w = tile_x + tx;
    const int pix = ((img * HH + h) * WW) + w;
    __half hb[RR];
    #pragma unroll
    for (int co = 0; co < RR; co++) hb[co] = __float2half_rn(acc[co]);
    uint4* oh = (uint4*)(mh + (size_t)pix * KP);
    oh[0] = ((uint4*)hb)[0];
    oh[1] = ((uint4*)hb)[1];
    uint4 z = make_uint4(0, 0, 0, 0);
    #pragma unroll
    for (int t = 2; t < 8; t++) oh[t] = z;
}

// ---------------------------------------------------------------------------
// Main HMMA GEMM: 128x128 CTA tile, 64x32 warp tiles, BK=64, 3-stage cp.async
// pipeline (13 chunks total incl. uniform LoRA chunk), fused bias epilogue.
// ---------------------------------------------------------------------------
__global__ void __launch_bounds__(256, 2) k_mma(const float* __restrict__ bqkv,
                                                float* __restrict__ out) {
    extern __shared__ char smem[];
    const uint32_t sbase = smem_u32(smem);
    const int tid = threadIdx.x;
    const int wid = tid >> 5, lane = tid & 31;
    const int wm = (wid & 1) * 64;
    const int wn = (wid >> 1) * 32;
    const int grp = lane >> 2, tig = lane & 3;

    const int n0 = blockIdx.x * 128;
    const int m0 = blockIdx.y * 128;
    const int region = (n0 < DIM) ? 0 : (n0 >= 2 * DIM ? 1 : -1);
    const int nr = n0 - (region == 1 ? 2 * DIM : 0);
    const int total = (region >= 0) ? 13 : 12;

    float acc[4][4][4];
    #pragma unroll
    for (int i = 0; i < 4; i++)
        #pragma unroll
        for (int j = 0; j < 4; j++)
            #pragma unroll
            for (int k = 0; k < 4; k++) acc[i][j][k] = 0.f;

    auto load_chunk = [&](int idx) {
        const __half *A, *B;
        int rsa, rsb;
        if (idx < 12) {
            A = g_xh + (size_t)m0 * DIM + idx * BK;
            B = g_wth + (size_t)n0 * DIM + idx * BK;
            rsa = DIM; rsb = DIM;
        } else {
            A = (region == 0 ? g_mqh : g_mvh) + (size_t)m0 * KP;
            B = (region == 0 ? g_wbtq : g_wbtv) + (size_t)nr * KP;
            rsa = KP; rsb = KP;
        }
        const uint32_t sa = sbase + (uint32_t)(idx % STAGES) * STAGE_BYTES;
        const uint32_t sb = sa + STAGE_A_BYTES;
        #pragma unroll
        for (int t = 0; t < 4; t++) {
            int i = tid + t * 256;
            int r = i >> 3, c = i & 7;
            uint32_t so = (uint32_t)(r * (APITCH * 2) + c * 16);
            cp16(sa + so, A + (size_t)r * rsa + c * 8);
            cp16(sb + so, B + (size_t)r * rsb + c * 8);
        }
        asm volatile("cp.async.commit_group;");
    };

    #pragma unroll
    for (int s = 0; s < STAGES - 1; s++) load_chunk(s);

    const uint32_t a_row = (uint32_t)(wm + (lane & 15));
    const uint32_t a_kof = (uint32_t)((lane >> 4) * 8);
    const uint32_t b_row = (uint32_t)(wn + (lane & 7) + ((lane >> 4) * 8));
    const uint32_t b_kof = (uint32_t)(((lane >> 3) & 1) * 8);

    for (int i = 0; i < total; i++) {
        asm volatile("cp.async.wait_group %0;" :: "n"(STAGES - 2));
        __syncthreads();
        if (i + STAGES - 1 < total) load_chunk(i + STAGES - 1);

        const uint32_t aBase = sbase + (uint32_t)(i % STAGES) * STAGE_BYTES;
        const uint32_t bBase = aBase + STAGE_A_BYTES;

        #pragma unroll
        for (int ks = 0; ks < 4; ks++) {
            uint32_t a[4][4], b[4][2];
            #pragma unroll
            for (int mi = 0; mi < 4; mi++) {
                uint32_t ad = aBase + ((a_row + mi * 16) * APITCH + ks * 16 + a_kof) * 2;
                ldm_x4(ad, a[mi][0], a[mi][1], a[mi][2], a[mi][3]);
            }
            #pragma unroll
            for (int nj = 0; nj < 2; nj++) {
                uint32_t bd = bBase + ((b_row + nj * 16) * APITCH + ks * 16 + b_kof) * 2;
                ldm_x4(bd, b[nj * 2][0], b[nj * 2][1], b[nj * 2 + 1][0], b[nj * 2 + 1][1]);
            }
            #pragma unroll
            for (int mi = 0; mi < 4; mi++)
                #pragma unroll
                for (int ni = 0; ni < 4; ni++)
                    mma16816(acc[mi][ni], a[mi], b[ni]);
        }
    }

    #pragma unroll
    for (int ni = 0; ni < 4; ni++) {
        const int n = n0 + wn + ni * 8 + 2 * tig;
        const float2 bv = *(const float2*)&bqkv[n];
        #pragma unroll
        for (int mi = 0; mi < 4; mi++) {
            const int m = m0 + wm + mi * 16 + grp;
            float2 v0 = make_float2(acc[mi][ni][0] + bv.x, acc[mi][ni][1] + bv.y);
            float2 v1 = make_float2(acc[mi][ni][2] + bv.x, acc[mi][ni][3] + bv.y);
            *(float2*)&out[(size_t)m * MOUT + n] = v0;
            *(float2*)&out[(size_t)(m + 8) * MOUT + n] = v1;
        }
    }
}

// ---------------------------------------------------------------------------
extern "C" void kernel_launch(void* const* d_in, const int* in_sizes, int n_in,
                              void* d_out, int out_size) {
    const float* x     = (const float*)d_in[0];
    const float* W_qkv = (const float*)d_in[1];
    const float* b_qkv = (const float*)d_in[2];
    const float* Wa_q  = (const float*)d_in[3];
    const float* Wb_q  = (const float*)d_in[4];
    const float* Wa_v  = (const float*)d_in[5];
    const float* Wb_v  = (const float*)d_in[6];
    const float* K_q3  = (const float*)d_in[7];
    const float* b_q3  = (const float*)d_in[8];
    const float* K_v3  = (const float*)d_in[9];
    const float* b_v3  = (const float*)d_in[10];
    const float* K_q1  = (const float*)d_in[11];
    const float* b_q1  = (const float*)d_in[12];
    const float* K_v1  = (const float*)d_in[13];
    const float* b_v1  = (const float*)d_in[14];
    float* out = (float*)d_out;

    cudaFuncSetAttribute(k_front, cudaFuncAttributeMaxDynamicSharedMemorySize, SMEM_FRONT);
    cudaFuncSetAttribute(k_mma, cudaFuncAttributeMaxDynamicSharedMemorySize, SMEM_MMA);

    k_front<<<FRONT_BLOCKS, 256, SMEM_FRONT>>>(x, Wa_q, Wa_v, W_qkv, Wb_q, Wb_v);
    k_conv<<<dim3(WW / 16, (HH / 16) * NB, 2), 256>>>(K_q3, b_q3, K_v3, b_v3,
                                                      K_q1, b_q1, K_v1, b_v1);
    k_mma<<<dim3(MOUT / 128, NPIX / 128), 256, SMEM_MMA>>>(b_qkv, out);
}